// round 5
// baseline (speedup 1.0000x reference)
#include <cuda_runtime.h>
#include <math.h>

#define DIM      128
#define N_EDGES  800000
#define META     20000
#define AUTHOR   50000
#define BATCH    8192
#define PAIRS    4096
#define HID      640

typedef unsigned long long ull;

// ---------------- device scratch (no allocations allowed) ----------------
__device__ float g_s0[AUTHOR * DIM];
__device__ float g_s1[AUTHOR * DIM];
__device__ float g_t0[AUTHOR];
__device__ float g_t1[AUTHOR];
__device__ unsigned char g_flag[AUTHOR];
__device__ __align__(16) float g_u0[132];   // u[128] + c at [128]
__device__ __align__(16) float g_u1[132];
// fused matrices, row-major: M[d*128 + k]
__device__ float g_M6[DIM * DIM];
__device__ float g_M9[DIM * DIM];
__device__ float g_M7[DIM * DIM];
__device__ float g_M10[DIM * DIM];
__device__ float g_M12[DIM * DIM];
__device__ float g_bf[DIM];
__device__ float g_h[BATCH * DIM];

// ---------------- packed f32x2 helpers ----------------
__device__ __forceinline__ ull pk(float lo, float hi) {
    ull r; asm("mov.b64 %0, {%1,%2};" : "=l"(r) : "f"(lo), "f"(hi)); return r;
}
__device__ __forceinline__ ull dup2(float v) { return pk(v, v); }
__device__ __forceinline__ ull ffma2(ull a, ull b, ull c) {
    ull r; asm("fma.rn.f32x2 %0, %1, %2, %3;" : "=l"(r) : "l"(a), "l"(b), "l"(c)); return r;
}
__device__ __forceinline__ float2 upk(ull v) {
    float2 f; asm("mov.b64 {%0,%1}, %2;" : "=f"(f.x), "=f"(f.y) : "l"(v)); return f;
}

// ---------------- fused setup kernel ----------------
#define ZB  196
#define UB  2
#define FB  320
#define BFB 128
#define OB  32
#define SETUP_BLOCKS (ZB + UB + FB + BFB + OB)

__global__ void __launch_bounds__(256) k_setup(
        const float* __restrict__ W3, const float* __restrict__ hp0, const float* __restrict__ b3,
        const float* __restrict__ W4, const float* __restrict__ hp1, const float* __restrict__ b4,
        const float* __restrict__ Wc, const float* __restrict__ bc,
        const float* __restrict__ W6, const float* __restrict__ b6,
        const float* __restrict__ W9, const float* __restrict__ b9,
        const float* __restrict__ W7, const float* __restrict__ b7,
        const float* __restrict__ W10, const float* __restrict__ b10,
        const float* __restrict__ W12, const float* __restrict__ b12,
        const float* __restrict__ b2, float* __restrict__ out) {
    __shared__ float red[256];
    int bx = blockIdx.x, tid = threadIdx.x;

    if (bx < ZB) {                                   // ---- zero flags
        int i = bx * 256 + tid;
        if (i < AUTHOR) g_flag[i] = 0;
        return;
    }
    bx -= ZB;
    if (bx < UB) {                                   // ---- u = W^T hp, c = b.hp
        const float* W  = bx ? W4  : W3;
        const float* hp = bx ? hp1 : hp0;
        const float* bb = bx ? b4  : b3;
        float* u = bx ? g_u1 : g_u0;
        int k = tid;
        if (k < DIM) {
            float a = 0.f;
            #pragma unroll 8
            for (int d = 0; d < DIM; d++) a += W[d * DIM + k] * hp[d];
            u[k] = a;
            red[k] = bb[k] * hp[k];
        }
        __syncthreads();
        if (k < DIM) {
            for (int s = 64; s; s >>= 1) {
                if (k < s) red[k] += red[k + s];
                __syncwarp(0xffffffffu);
                if (s > 32) __syncthreads();
            }
            if (k == 0) u[DIM] = red[0];
        }
        return;
    }
    bx -= UB;
    if (bx < FB) {                                   // ---- fused M matrices
        int m = bx / 64;
        const float* R; float* M; int seg;
        switch (m) {
            case 0:  R = W6;  M = g_M6;  seg = 0; break;
            case 1:  R = W9;  M = g_M9;  seg = 0; break;
            case 2:  R = W7;  M = g_M7;  seg = 1; break;
            case 3:  R = W10; M = g_M10; seg = 1; break;
            default: R = W12; M = g_M12; seg = 2; break;
        }
        int o = (bx % 64) * 256 + tid;
        int d = o >> 7, k = o & 127;
        const float* wrow = Wc + (size_t)d * 384 + seg * 128;
        float a = 0.f;
        #pragma unroll 8
        for (int j = 0; j < DIM; j++) a += wrow[j] * R[j * DIM + k];
        M[o] = a;
        return;
    }
    bx -= FB;
    if (bx < BFB) {                                  // ---- fused bias
        int i = bx;
        const float* w = Wc + (size_t)i * 384;
        float a = 0.f;
        {
            int j = tid;
            float v = (j < 128) ? (b6[j] + b9[j]) : (b7[j - 128] + b10[j - 128]);
            a = w[j] * v;
            if (tid < 128) a += w[256 + tid] * b12[tid];
        }
        red[tid] = a;
        __syncthreads();
        for (int s = 128; s > 32; s >>= 1) {
            if (tid < s) red[tid] += red[tid + s];
            __syncthreads();
        }
        if (tid < 32) {
            float v = red[tid] + red[tid + 32];
            #pragma unroll
            for (int o = 16; o; o >>= 1) v += __shfl_xor_sync(0xffffffffu, v, o);
            if (tid == 0) g_bf[i] = v + bc[i];
        }
        return;
    }
    bx -= BFB;
    {                                                // ---- init out with b2
        int idx = bx * 256 + tid;
        out[idx] = b2[idx & 1];
    }
}

// mark needed author rows; zero their accumulators
__global__ void k_mark(const int* __restrict__ data) {
    int tid = blockIdx.x * blockDim.x + threadIdx.x;
    int b = tid >> 7, d = tid & 127;
    int r = data[b];
    g_s0[(size_t)r * DIM + d] = 0.f;
    g_s1[(size_t)r * DIM + d] = 0.f;
    if (d == 0) { g_t0[r] = 0.f; g_t1[r] = 0.f; g_flag[r] = 1; }
}

// ---------------- edge kernel: filter + weighted scatter (both graphs) ----------------
__global__ void k_edges(const int* __restrict__ ei0, const float* __restrict__ iv0,
                        const float* __restrict__ sem0,
                        const int* __restrict__ ei1, const float* __restrict__ iv1,
                        const float* __restrict__ sem1) {
    int which = blockIdx.y;
    const int*   rows = which ? ei1 : ei0;
    const int*   cols = (which ? ei1 : ei0) + N_EDGES;
    const float* interval = which ? iv1 : iv0;
    const float* sem = which ? sem1 : sem0;
    const float* u = which ? g_u1 : g_u0;
    float* s = which ? g_s1 : g_s0;
    float* t = which ? g_t1 : g_t0;

    int lane = threadIdx.x & 31;
    int base = (blockIdx.x * (blockDim.x >> 5) + (threadIdx.x >> 5)) * 32;
    if (base >= N_EDGES) return;

    int e = base + lane;
    int r = -1; bool ok = false;
    if (e < N_EDGES) {
        int row = rows[e];
        r = row - META;
        ok = ((unsigned)r < (unsigned)AUTHOR) && g_flag[r];
    }
    unsigned m = __ballot_sync(0xffffffffu, ok);
    if (!m) return;

    float4 uv = ((const float4*)u)[lane];
    float c = u[DIM];
    while (m) {
        int src = __ffs(m) - 1; m &= (m - 1);
        int rr = __shfl_sync(0xffffffffu, r, src);
        int ee = base + src;
        int col = cols[ee];
        float iv = interval[ee];
        float4 x = ((const float4*)(sem + (size_t)col * DIM))[lane];
        float p = x.x * uv.x + x.y * uv.y + x.z * uv.z + x.w * uv.w;
        #pragma unroll
        for (int o = 16; o; o >>= 1) p += __shfl_xor_sync(0xffffffffu, p, o);
        float w = __expf(iv * (p + c));
        float* sp = s + (size_t)rr * DIM + lane * 4;
        asm volatile("red.global.add.v4.f32 [%0], {%1, %2, %3, %4};"
                     :: "l"(sp), "f"(w * x.x), "f"(w * x.y), "f"(w * x.z), "f"(w * x.w)
                     : "memory");
        if (lane == 0) atomicAdd(&t[rr], w);
    }
}

// ---------------- fused dense stage (both sides + structure branch) ----------------
// 16 samples/block, 512 blocks; slot = tid>>7 handles 8 samples (4 packed accs)
#define BS     16
#define HALFS  8
#define PITCH  12
#define SLOTSZ (DIM * PITCH)

__device__ __forceinline__ void mat_pass(ull acc[4], const float* __restrict__ M,
                                         int d, const float* __restrict__ mybuf) {
    const float4* mr = (const float4*)(M + (size_t)d * DIM);
    #pragma unroll 4
    for (int kk = 0; kk < 32; kk++) {
        float4 w4 = mr[kk];
        #pragma unroll
        for (int c = 0; c < 4; c++) {
            float wv = (c == 0) ? w4.x : (c == 1) ? w4.y : (c == 2) ? w4.z : w4.w;
            ull wd = dup2(wv);
            const ulonglong2* xp = (const ulonglong2*)(mybuf + (4 * kk + c) * PITCH);
            #pragma unroll
            for (int j4 = 0; j4 < 2; j4++) {
                ulonglong2 v = xp[j4];
                acc[2 * j4]     = ffma2(wd, v.x, acc[2 * j4]);
                acc[2 * j4 + 1] = ffma2(wd, v.y, acc[2 * j4 + 1]);
            }
        }
    }
}

__global__ void __launch_bounds__(256) k_both(
        const float* __restrict__ W3, const float* __restrict__ b3, const float* __restrict__ c0,
        const float* __restrict__ W4, const float* __restrict__ b4, const float* __restrict__ c1,
        const float* __restrict__ st, const int* __restrict__ data) {
    __shared__ __align__(16) float buf[2 * SLOTSZ];   // 12288 B
    __shared__ float ts0[BS], ts1[BS];
    __shared__ int   rs[BS];

    int tid = threadIdx.x;
    int slot = tid >> 7, d = tid & 127;
    int bb = blockIdx.x * BS;

    if (tid < BS) {
        int r = data[bb + tid];
        rs[tid] = r;
        ts0[tid] = g_t0[r];
        ts1[tid] = g_t1[r];
    }
    __syncthreads();

    float* mybuf = buf + slot * SLOTSZ;
    int sb = slot * HALFS;

    ull h2[4];
    #pragma unroll
    for (int j = 0; j < 4; j++) h2[j] = pk(0.f, 0.f);
    ull acc[4];

    // ===== side 0 =====
    for (int i = tid; i < BS * DIM; i += 256) {
        int spl = i >> 7, k = i & 127;
        buf[(spl >> 3) * SLOTSZ + k * PITCH + (spl & 7)] = g_s0[(size_t)rs[spl] * DIM + k];
    }
    __syncthreads();
    {
        float bwd = b3[d];
        #pragma unroll
        for (int j = 0; j < 4; j++)
            acc[j] = pk(ts0[sb + 2 * j] * bwd, ts0[sb + 2 * j + 1] * bwd);
        mat_pass(acc, W3, d, mybuf);
    }
    __syncthreads();
    #pragma unroll
    for (int j = 0; j < 4; j++) {
        float2 gv = upk(acc[j]);
        *(ull*)(mybuf + d * PITCH + 2 * j) = pk(fmaxf(gv.x, 0.f), fmaxf(gv.y, 0.f));
    }
    __syncthreads();
    mat_pass(h2, g_M6, d, mybuf);
    __syncthreads();
    for (int i = tid; i < BS * DIM; i += 256) {
        int spl = i >> 7, k = i & 127;
        buf[(spl >> 3) * SLOTSZ + k * PITCH + (spl & 7)] = c0[(size_t)(bb + spl) * DIM + k];
    }
    __syncthreads();
    mat_pass(h2, g_M9, d, mybuf);
    __syncthreads();

    // ===== side 1 =====
    for (int i = tid; i < BS * DIM; i += 256) {
        int spl = i >> 7, k = i & 127;
        buf[(spl >> 3) * SLOTSZ + k * PITCH + (spl & 7)] = g_s1[(size_t)rs[spl] * DIM + k];
    }
    __syncthreads();
    {
        float bwd = b4[d];
        #pragma unroll
        for (int j = 0; j < 4; j++)
            acc[j] = pk(ts1[sb + 2 * j] * bwd, ts1[sb + 2 * j + 1] * bwd);
        mat_pass(acc, W4, d, mybuf);
    }
    __syncthreads();
    #pragma unroll
    for (int j = 0; j < 4; j++) {
        float2 gv = upk(acc[j]);
        *(ull*)(mybuf + d * PITCH + 2 * j) = pk(fmaxf(gv.x, 0.f), fmaxf(gv.y, 0.f));
    }
    __syncthreads();
    mat_pass(h2, g_M7, d, mybuf);
    __syncthreads();
    for (int i = tid; i < BS * DIM; i += 256) {
        int spl = i >> 7, k = i & 127;
        buf[(spl >> 3) * SLOTSZ + k * PITCH + (spl & 7)] = c1[(size_t)(bb + spl) * DIM + k];
    }
    __syncthreads();
    mat_pass(h2, g_M10, d, mybuf);
    __syncthreads();

    // ===== structure branch + relu =====
    for (int i = tid; i < BS * DIM; i += 256) {
        int spl = i >> 7, k = i & 127;
        buf[(spl >> 3) * SLOTSZ + k * PITCH + (spl & 7)] = st[(size_t)(bb + spl) * DIM + k];
    }
    __syncthreads();
    mat_pass(h2, g_M12, d, mybuf);
    float bfd = g_bf[d];
    #pragma unroll
    for (int j = 0; j < 4; j++) {
        float2 hv = upk(h2[j]);
        g_h[(size_t)(bb + sb + 2 * j) * DIM + d]     = fmaxf(hv.x + bfd, 0.f);
        g_h[(size_t)(bb + sb + 2 * j + 1) * DIM + d] = fmaxf(hv.y + bfd, 0.f);
    }
}

// ---------------- pair stage, split over z-quarters; atomic combine ----------------
#define DPITCH 66
#define HQ     (HID / 4)
__global__ void __launch_bounds__(256) k_pairs(
        const float* __restrict__ W1, const float* __restrict__ b1,
        const float* __restrict__ W2,
        float* __restrict__ out) {
    __shared__ __align__(16) float dT[DIM * DPITCH];
    __shared__ float w1c[8 * DIM];
    __shared__ ull red0[8][32];
    __shared__ ull red1[8][32];

    int tid = threadIdx.x;
    int p = tid & 31, zs = tid >> 5;
    int pbase = blockIdx.x * 64;
    int zbase = blockIdx.y * HQ;

    for (int e = tid; e < 8192; e += 256) {
        int pp = e >> 7, k = e & 127;
        float a  = g_h[(size_t)(pbase + pp) * DIM + k];
        float bq = g_h[(size_t)(pbase + pp + PAIRS) * DIM + k];
        dT[k * DPITCH + pp] = fabsf(a - bq);
    }
    __syncthreads();

    ull o0 = pk(0.f, 0.f), o1 = pk(0.f, 0.f);
    const ull* drow = (const ull*)dT;
    for (int zc = 0; zc < HQ / 8; zc++) {
        for (int e = tid; e < 1024; e += 256) {
            int zz = e >> 7, k = e & 127;
            w1c[zz * DIM + k] = W1[(size_t)(zbase + zc * 8 + zz) * DIM + k];
        }
        __syncthreads();
        ull acc = pk(0.f, 0.f);
        #pragma unroll 8
        for (int k = 0; k < DIM; k++)
            acc = ffma2(dup2(w1c[zs * DIM + k]), drow[k * (DPITCH / 2) + p], acc);
        int z = zbase + zc * 8 + zs;
        float bz = b1[z];
        float2 av = upk(acc);
        ull zv = pk(fmaxf(av.x + bz, 0.f), fmaxf(av.y + bz, 0.f));
        o0 = ffma2(dup2(W2[z]),       zv, o0);
        o1 = ffma2(dup2(W2[HID + z]), zv, o1);
        __syncthreads();
    }
    red0[zs][p] = o0; red1[zs][p] = o1;
    __syncthreads();
    if (zs == 0) {
        float a0 = 0.f, a1 = 0.f, c0 = 0.f, c1 = 0.f;
        #pragma unroll
        for (int j = 0; j < 8; j++) {
            float2 v0 = upk(red0[j][p]); a0 += v0.x; c0 += v0.y;
            float2 v1 = upk(red1[j][p]); a1 += v1.x; c1 += v1.y;
        }
        int q0 = pbase + 2 * p, q1 = q0 + 1;
        atomicAdd(&out[(size_t)q0 * 2 + 0], a0);
        atomicAdd(&out[(size_t)q0 * 2 + 1], a1);
        atomicAdd(&out[(size_t)q1 * 2 + 0], c0);
        atomicAdd(&out[(size_t)q1 * 2 + 1], c1);
    }
}

// ---------------- launch ----------------
extern "C" void kernel_launch(void* const* d_in, const int* in_sizes, int n_in,
                              void* d_out, int out_size) {
    const float* sem0 = (const float*)d_in[0];
    const float* iv0  = (const float*)d_in[1];
    const int*   ei0  = (const int*)  d_in[2];
    const float* sem1 = (const float*)d_in[3];
    const float* iv1  = (const float*)d_in[4];
    const int*   ei1  = (const int*)  d_in[5];
    const float* c0   = (const float*)d_in[6];
    const float* c1   = (const float*)d_in[7];
    const int*   data = (const int*)  d_in[8];
    const float* st   = (const float*)d_in[9];
    const float* W1  = (const float*)d_in[10]; const float* b1  = (const float*)d_in[11];
    const float* W2  = (const float*)d_in[12]; const float* b2  = (const float*)d_in[13];
    const float* W3  = (const float*)d_in[14]; const float* b3  = (const float*)d_in[15];
    const float* W4  = (const float*)d_in[16]; const float* b4  = (const float*)d_in[17];
    const float* W6  = (const float*)d_in[18]; const float* b6  = (const float*)d_in[19];
    const float* W7  = (const float*)d_in[20]; const float* b7  = (const float*)d_in[21];
    const float* W9  = (const float*)d_in[22]; const float* b9  = (const float*)d_in[23];
    const float* W10 = (const float*)d_in[24]; const float* b10 = (const float*)d_in[25];
    const float* W12 = (const float*)d_in[26]; const float* b12 = (const float*)d_in[27];
    const float* Wc  = (const float*)d_in[28]; const float* bc  = (const float*)d_in[29];
    const float* hp0 = (const float*)d_in[30]; const float* hp1 = (const float*)d_in[31];
    float* out = (float*)d_out;

    k_setup<<<SETUP_BLOCKS, 256>>>(W3, hp0, b3, W4, hp1, b4, Wc, bc,
                                   W6, b6, W9, b9, W7, b7, W10, b10, W12, b12,
                                   b2, out);
    k_mark<<<(BATCH * DIM) / 256, 256>>>(data);

    int eblocks = (N_EDGES / 32 + 7) / 8;
    k_edges<<<dim3(eblocks, 2), 256>>>(ei0, iv0, sem0, ei1, iv1, sem1);

    k_both<<<BATCH / BS, 256>>>(W3, b3, c0, W4, b4, c1, st, data);

    k_pairs<<<dim3(PAIRS / 64, 4), 256>>>(W1, b1, W2, out);
    (void)in_sizes; (void)n_in; (void)out_size;
}

// round 8
// speedup vs baseline: 1.4118x; 1.4118x over previous
#include <cuda_runtime.h>
#include <math.h>

#define DIM      128
#define N_EDGES  800000
#define META     20000
#define AUTHOR   50000
#define BATCH    8192
#define PAIRS    4096
#define HID      640

typedef unsigned long long ull;

// ---------------- device scratch (no allocations allowed) ----------------
__device__ float g_s0[AUTHOR * DIM];
__device__ float g_s1[AUTHOR * DIM];
__device__ float g_t0[AUTHOR];
__device__ float g_t1[AUTHOR];
__device__ unsigned char g_flag[AUTHOR];
__device__ __align__(16) float g_u0[132];   // u[128] + c at [128]
__device__ __align__(16) float g_u1[132];
// k-major matrices: M[k*128 + d]  (coalesced per-warp weight loads in k_both)
__device__ float g_W3T[DIM * DIM];
__device__ float g_W4T[DIM * DIM];
__device__ float g_M6[DIM * DIM];
__device__ float g_M9[DIM * DIM];
__device__ float g_M7[DIM * DIM];
__device__ float g_M10[DIM * DIM];
__device__ float g_M12[DIM * DIM];
__device__ float g_bf[DIM];
__device__ float g_h[BATCH * DIM];

// ---------------- packed f32x2 helpers ----------------
__device__ __forceinline__ ull pk(float lo, float hi) {
    ull r; asm("mov.b64 %0, {%1,%2};" : "=l"(r) : "f"(lo), "f"(hi)); return r;
}
__device__ __forceinline__ ull dup2(float v) { return pk(v, v); }
__device__ __forceinline__ ull ffma2(ull a, ull b, ull c) {
    ull r; asm("fma.rn.f32x2 %0, %1, %2, %3;" : "=l"(r) : "l"(a), "l"(b), "l"(c)); return r;
}
__device__ __forceinline__ float2 upk(ull v) {
    float2 f; asm("mov.b64 {%0,%1}, %2;" : "=f"(f.x), "=f"(f.y) : "l"(v)); return f;
}

// ---------------- fused setup kernel ----------------
#define ZB  196
#define UB  2
#define FB  320
#define TB  128
#define BFB 128
#define OB  32
#define SETUP_BLOCKS (ZB + UB + FB + TB + BFB + OB)

__global__ void __launch_bounds__(256) k_setup(
        const float* __restrict__ W3, const float* __restrict__ hp0, const float* __restrict__ b3,
        const float* __restrict__ W4, const float* __restrict__ hp1, const float* __restrict__ b4,
        const float* __restrict__ Wc, const float* __restrict__ bc,
        const float* __restrict__ W6, const float* __restrict__ b6,
        const float* __restrict__ W9, const float* __restrict__ b9,
        const float* __restrict__ W7, const float* __restrict__ b7,
        const float* __restrict__ W10, const float* __restrict__ b10,
        const float* __restrict__ W12, const float* __restrict__ b12,
        const float* __restrict__ b2, float* __restrict__ out) {
    __shared__ float red[256];
    int bx = blockIdx.x, tid = threadIdx.x;

    if (bx < ZB) {                                   // ---- zero flags
        int i = bx * 256 + tid;
        if (i < AUTHOR) g_flag[i] = 0;
        return;
    }
    bx -= ZB;
    if (bx < UB) {                                   // ---- u = W^T hp, c = b.hp
        const float* W  = bx ? W4  : W3;
        const float* hp = bx ? hp1 : hp0;
        const float* bb = bx ? b4  : b3;
        float* u = bx ? g_u1 : g_u0;
        int k = tid;
        if (k < DIM) {
            float a = 0.f;
            #pragma unroll 8
            for (int d = 0; d < DIM; d++) a += W[d * DIM + k] * hp[d];
            u[k] = a;
            red[k] = bb[k] * hp[k];
        }
        __syncthreads();
        if (k < DIM) {
            for (int s = 64; s; s >>= 1) {
                if (k < s) red[k] += red[k + s];
                __syncwarp(0xffffffffu);
                if (s > 32) __syncthreads();
            }
            if (k == 0) u[DIM] = red[0];
        }
        return;
    }
    bx -= UB;
    if (bx < FB) {                                   // ---- fused M matrices (k-major store)
        int m = bx / 64;
        const float* R; float* M; int seg;
        switch (m) {
            case 0:  R = W6;  M = g_M6;  seg = 0; break;
            case 1:  R = W9;  M = g_M9;  seg = 0; break;
            case 2:  R = W7;  M = g_M7;  seg = 1; break;
            case 3:  R = W10; M = g_M10; seg = 1; break;
            default: R = W12; M = g_M12; seg = 2; break;
        }
        int o = (bx % 64) * 256 + tid;
        int d = o >> 7, k = o & 127;
        const float* wrow = Wc + (size_t)d * 384 + seg * 128;
        float a = 0.f;
        #pragma unroll 8
        for (int j = 0; j < DIM; j++) a += wrow[j] * R[j * DIM + k];
        M[k * DIM + d] = a;
        return;
    }
    bx -= FB;
    if (bx < TB) {                                   // ---- transpose W3, W4 to k-major
        int m = bx / 64;
        const float* W = m ? W4 : W3;
        float* T = m ? g_W4T : g_W3T;
        int o = (bx % 64) * 256 + tid;
        int d = o >> 7, k = o & 127;
        T[k * DIM + d] = W[o];
        return;
    }
    bx -= TB;
    if (bx < BFB) {                                  // ---- fused bias
        int i = bx;
        const float* w = Wc + (size_t)i * 384;
        float a = 0.f;
        {
            int j = tid;
            float v = (j < 128) ? (b6[j] + b9[j]) : (b7[j - 128] + b10[j - 128]);
            a = w[j] * v;
            if (tid < 128) a += w[256 + tid] * b12[tid];
        }
        red[tid] = a;
        __syncthreads();
        for (int s = 128; s > 32; s >>= 1) {
            if (tid < s) red[tid] += red[tid + s];
            __syncthreads();
        }
        if (tid < 32) {
            float v = red[tid] + red[tid + 32];
            #pragma unroll
            for (int o = 16; o; o >>= 1) v += __shfl_xor_sync(0xffffffffu, v, o);
            if (tid == 0) g_bf[i] = v + bc[i];
        }
        return;
    }
    bx -= BFB;
    {                                                // ---- init out with b2
        int idx = bx * 256 + tid;
        out[idx] = b2[idx & 1];
    }
}

// mark needed author rows; zero their accumulators
__global__ void k_mark(const int* __restrict__ data) {
    int tid = blockIdx.x * blockDim.x + threadIdx.x;
    int b = tid >> 7, d = tid & 127;
    int r = data[b];
    g_s0[(size_t)r * DIM + d] = 0.f;
    g_s1[(size_t)r * DIM + d] = 0.f;
    if (d == 0) { g_t0[r] = 0.f; g_t1[r] = 0.f; g_flag[r] = 1; }
}

// ---------------- edge kernel: filter + weighted scatter (both graphs) ----------------
__global__ void k_edges(const int* __restrict__ ei0, const float* __restrict__ iv0,
                        const float* __restrict__ sem0,
                        const int* __restrict__ ei1, const float* __restrict__ iv1,
                        const float* __restrict__ sem1) {
    int which = blockIdx.y;
    const int*   rows = which ? ei1 : ei0;
    const int*   cols = (which ? ei1 : ei0) + N_EDGES;
    const float* interval = which ? iv1 : iv0;
    const float* sem = which ? sem1 : sem0;
    const float* u = which ? g_u1 : g_u0;
    float* s = which ? g_s1 : g_s0;
    float* t = which ? g_t1 : g_t0;

    int lane = threadIdx.x & 31;
    int base = (blockIdx.x * (blockDim.x >> 5) + (threadIdx.x >> 5)) * 32;
    if (base >= N_EDGES) return;

    int e = base + lane;
    int r = -1; bool ok = false;
    if (e < N_EDGES) {
        int row = rows[e];
        r = row - META;
        ok = ((unsigned)r < (unsigned)AUTHOR) && g_flag[r];
    }
    unsigned m = __ballot_sync(0xffffffffu, ok);
    if (!m) return;

    float4 uv = ((const float4*)u)[lane];
    float c = u[DIM];
    while (m) {
        int src = __ffs(m) - 1; m &= (m - 1);
        int rr = __shfl_sync(0xffffffffu, r, src);
        int ee = base + src;
        int col = cols[ee];
        float iv = interval[ee];
        float4 x = ((const float4*)(sem + (size_t)col * DIM))[lane];
        float p = x.x * uv.x + x.y * uv.y + x.z * uv.z + x.w * uv.w;
        #pragma unroll
        for (int o = 16; o; o >>= 1) p += __shfl_xor_sync(0xffffffffu, p, o);
        float w = __expf(iv * (p + c));
        float* sp = s + (size_t)rr * DIM + lane * 4;
        asm volatile("red.global.add.v4.f32 [%0], {%1, %2, %3, %4};"
                     :: "l"(sp), "f"(w * x.x), "f"(w * x.y), "f"(w * x.z), "f"(w * x.w)
                     : "memory");
        if (lane == 0) atomicAdd(&t[rr], w);
    }
}

// ---------------- fused dense stage (both sides + structure branch) ----------------
// 32 samples/block, 256 blocks; slot = tid>>7 handles 16 samples (8 packed accs)
// weights k-major -> coalesced scalar LDG (1 wavefront/warp/k)
#define BS     32
#define HALFS  16
#define PITCH  20
#define SLOTSZ (DIM * PITCH)

__device__ __forceinline__ void mat_pass(ull acc[8], const float* __restrict__ Mt,
                                         int d, const float* __restrict__ mybuf) {
    #pragma unroll 8
    for (int k = 0; k < DIM; k++) {
        ull wd = dup2(Mt[(size_t)k * DIM + d]);
        const ulonglong2* xp = (const ulonglong2*)(mybuf + k * PITCH);
        ulonglong2 va = xp[0], vb = xp[1], vc = xp[2], ve = xp[3];
        acc[0] = ffma2(wd, va.x, acc[0]);
        acc[1] = ffma2(wd, va.y, acc[1]);
        acc[2] = ffma2(wd, vb.x, acc[2]);
        acc[3] = ffma2(wd, vb.y, acc[3]);
        acc[4] = ffma2(wd, vc.x, acc[4]);
        acc[5] = ffma2(wd, vc.y, acc[5]);
        acc[6] = ffma2(wd, ve.x, acc[6]);
        acc[7] = ffma2(wd, ve.y, acc[7]);
    }
}

__global__ void __launch_bounds__(256) k_both(
        const float* __restrict__ b3, const float* __restrict__ c0,
        const float* __restrict__ b4, const float* __restrict__ c1,
        const float* __restrict__ st, const int* __restrict__ data) {
    __shared__ __align__(16) float buf[2 * SLOTSZ];   // 20480 B
    __shared__ float ts0[BS], ts1[BS];
    __shared__ int   rs[BS];

    int tid = threadIdx.x;
    int slot = tid >> 7, d = tid & 127;
    int bb = blockIdx.x * BS;

    if (tid < BS) {
        int r = data[bb + tid];
        rs[tid] = r;
        ts0[tid] = g_t0[r];
        ts1[tid] = g_t1[r];
    }
    __syncthreads();

    float* mybuf = buf + slot * SLOTSZ;
    int sb = slot * HALFS;

    ull h2[8];
    #pragma unroll
    for (int j = 0; j < 8; j++) h2[j] = pk(0.f, 0.f);
    ull acc[8];

    // ===== side 0 =====
    for (int i = tid; i < BS * DIM; i += 256) {
        int spl = i >> 7, k = i & 127;
        buf[(spl >> 4) * SLOTSZ + k * PITCH + (spl & 15)] = g_s0[(size_t)rs[spl] * DIM + k];
    }
    __syncthreads();
    {
        float bwd = b3[d];
        #pragma unroll
        for (int j = 0; j < 8; j++)
            acc[j] = pk(ts0[sb + 2 * j] * bwd, ts0[sb + 2 * j + 1] * bwd);
        mat_pass(acc, g_W3T, d, mybuf);
    }
    __syncthreads();
    #pragma unroll
    for (int j = 0; j < 8; j++) {
        float2 gv = upk(acc[j]);
        *(ull*)(mybuf + d * PITCH + 2 * j) = pk(fmaxf(gv.x, 0.f), fmaxf(gv.y, 0.f));
    }
    __syncthreads();
    mat_pass(h2, g_M6, d, mybuf);
    __syncthreads();
    for (int i = tid; i < BS * DIM; i += 256) {
        int spl = i >> 7, k = i & 127;
        buf[(spl >> 4) * SLOTSZ + k * PITCH + (spl & 15)] = c0[(size_t)(bb + spl) * DIM + k];
    }
    __syncthreads();
    mat_pass(h2, g_M9, d, mybuf);
    __syncthreads();

    // ===== side 1 =====
    for (int i = tid; i < BS * DIM; i += 256) {
        int spl = i >> 7, k = i & 127;
        buf[(spl >> 4) * SLOTSZ + k * PITCH + (spl & 15)] = g_s1[(size_t)rs[spl] * DIM + k];
    }
    __syncthreads();
    {
        float bwd = b4[d];
        #pragma unroll
        for (int j = 0; j < 8; j++)
            acc[j] = pk(ts1[sb + 2 * j] * bwd, ts1[sb + 2 * j + 1] * bwd);
        mat_pass(acc, g_W4T, d, mybuf);
    }
    __syncthreads();
    #pragma unroll
    for (int j = 0; j < 8; j++) {
        float2 gv = upk(acc[j]);
        *(ull*)(mybuf + d * PITCH + 2 * j) = pk(fmaxf(gv.x, 0.f), fmaxf(gv.y, 0.f));
    }
    __syncthreads();
    mat_pass(h2, g_M7, d, mybuf);
    __syncthreads();
    for (int i = tid; i < BS * DIM; i += 256) {
        int spl = i >> 7, k = i & 127;
        buf[(spl >> 4) * SLOTSZ + k * PITCH + (spl & 15)] = c1[(size_t)(bb + spl) * DIM + k];
    }
    __syncthreads();
    mat_pass(h2, g_M10, d, mybuf);
    __syncthreads();

    // ===== structure branch + relu =====
    for (int i = tid; i < BS * DIM; i += 256) {
        int spl = i >> 7, k = i & 127;
        buf[(spl >> 4) * SLOTSZ + k * PITCH + (spl & 15)] = st[(size_t)(bb + spl) * DIM + k];
    }
    __syncthreads();
    mat_pass(h2, g_M12, d, mybuf);
    float bfd = g_bf[d];
    #pragma unroll
    for (int j = 0; j < 8; j++) {
        float2 hv = upk(h2[j]);
        g_h[(size_t)(bb + sb + 2 * j) * DIM + d]     = fmaxf(hv.x + bfd, 0.f);
        g_h[(size_t)(bb + sb + 2 * j + 1) * DIM + d] = fmaxf(hv.y + bfd, 0.f);
    }
}

// ---------------- pair stage, split over z-quarters; atomic combine ----------------
#define DPITCH 66
#define HQ     (HID / 4)
__global__ void __launch_bounds__(256) k_pairs(
        const float* __restrict__ W1, const float* __restrict__ b1,
        const float* __restrict__ W2,
        float* __restrict__ out) {
    __shared__ __align__(16) float dT[DIM * DPITCH];
    __shared__ float w1c[8 * DIM];
    __shared__ ull red0[8][32];
    __shared__ ull red1[8][32];

    int tid = threadIdx.x;
    int p = tid & 31, zs = tid >> 5;
    int pbase = blockIdx.x * 64;
    int zbase = blockIdx.y * HQ;

    for (int e = tid; e < 8192; e += 256) {
        int pp = e >> 7, k = e & 127;
        float a  = g_h[(size_t)(pbase + pp) * DIM + k];
        float bq = g_h[(size_t)(pbase + pp + PAIRS) * DIM + k];
        dT[k * DPITCH + pp] = fabsf(a - bq);
    }
    __syncthreads();

    ull o0 = pk(0.f, 0.f), o1 = pk(0.f, 0.f);
    const ull* drow = (const ull*)dT;
    for (int zc = 0; zc < HQ / 8; zc++) {
        for (int e = tid; e < 1024; e += 256) {
            int zz = e >> 7, k = e & 127;
            w1c[zz * DIM + k] = W1[(size_t)(zbase + zc * 8 + zz) * DIM + k];
        }
        __syncthreads();
        ull acc = pk(0.f, 0.f);
        #pragma unroll 8
        for (int k = 0; k < DIM; k++)
            acc = ffma2(dup2(w1c[zs * DIM + k]), drow[k * (DPITCH / 2) + p], acc);
        int z = zbase + zc * 8 + zs;
        float bz = b1[z];
        float2 av = upk(acc);
        ull zv = pk(fmaxf(av.x + bz, 0.f), fmaxf(av.y + bz, 0.f));
        o0 = ffma2(dup2(W2[z]),       zv, o0);
        o1 = ffma2(dup2(W2[HID + z]), zv, o1);
        __syncthreads();
    }
    red0[zs][p] = o0; red1[zs][p] = o1;
    __syncthreads();
    if (zs == 0) {
        float a0 = 0.f, a1 = 0.f, c0 = 0.f, c1 = 0.f;
        #pragma unroll
        for (int j = 0; j < 8; j++) {
            float2 v0 = upk(red0[j][p]); a0 += v0.x; c0 += v0.y;
            float2 v1 = upk(red1[j][p]); a1 += v1.x; c1 += v1.y;
        }
        int q0 = pbase + 2 * p, q1 = q0 + 1;
        atomicAdd(&out[(size_t)q0 * 2 + 0], a0);
        atomicAdd(&out[(size_t)q0 * 2 + 1], a1);
        atomicAdd(&out[(size_t)q1 * 2 + 0], c0);
        atomicAdd(&out[(size_t)q1 * 2 + 1], c1);
    }
}

// ---------------- launch ----------------
extern "C" void kernel_launch(void* const* d_in, const int* in_sizes, int n_in,
                              void* d_out, int out_size) {
    const float* sem0 = (const float*)d_in[0];
    const float* iv0  = (const float*)d_in[1];
    const int*   ei0  = (const int*)  d_in[2];
    const float* sem1 = (const float*)d_in[3];
    const float* iv1  = (const float*)d_in[4];
    const int*   ei1  = (const int*)  d_in[5];
    const float* c0   = (const float*)d_in[6];
    const float* c1   = (const float*)d_in[7];
    const int*   data = (const int*)  d_in[8];
    const float* st   = (const float*)d_in[9];
    const float* W1  = (const float*)d_in[10]; const float* b1  = (const float*)d_in[11];
    const float* W2  = (const float*)d_in[12]; const float* b2  = (const float*)d_in[13];
    const float* W3  = (const float*)d_in[14]; const float* b3  = (const float*)d_in[15];
    const float* W4  = (const float*)d_in[16]; const float* b4  = (const float*)d_in[17];
    const float* W6  = (const float*)d_in[18]; const float* b6  = (const float*)d_in[19];
    const float* W7  = (const float*)d_in[20]; const float* b7  = (const float*)d_in[21];
    const float* W9  = (const float*)d_in[22]; const float* b9  = (const float*)d_in[23];
    const float* W10 = (const float*)d_in[24]; const float* b10 = (const float*)d_in[25];
    const float* W12 = (const float*)d_in[26]; const float* b12 = (const float*)d_in[27];
    const float* Wc  = (const float*)d_in[28]; const float* bc  = (const float*)d_in[29];
    const float* hp0 = (const float*)d_in[30]; const float* hp1 = (const float*)d_in[31];
    float* out = (float*)d_out;

    k_setup<<<SETUP_BLOCKS, 256>>>(W3, hp0, b3, W4, hp1, b4, Wc, bc,
                                   W6, b6, W9, b9, W7, b7, W10, b10, W12, b12,
                                   b2, out);
    k_mark<<<(BATCH * DIM) / 256, 256>>>(data);

    int eblocks = (N_EDGES / 32 + 7) / 8;
    k_edges<<<dim3(eblocks, 2), 256>>>(ei0, iv0, sem0, ei1, iv1, sem1);

    k_both<<<BATCH / BS, 256>>>(b3, c0, b4, c1, st, data);

    k_pairs<<<dim3(PAIRS / 64, 4), 256>>>(W1, b1, W2, out);
    (void)in_sizes; (void)n_in; (void)out_size;
}

// round 9
// speedup vs baseline: 1.5350x; 1.0872x over previous
#include <cuda_runtime.h>
#include <math.h>
#include <cooperative_groups.h>
#include <cooperative_groups/reduce.h>

namespace cg = cooperative_groups;

#define DIM      128
#define N_EDGES  800000
#define META     20000
#define AUTHOR   50000
#define BATCH    8192
#define PAIRS    4096
#define HID      640

typedef unsigned long long ull;

// ---------------- device scratch (no allocations allowed) ----------------
__device__ float g_s0[AUTHOR * DIM];
__device__ float g_s1[AUTHOR * DIM];
__device__ float g_t0[AUTHOR];
__device__ float g_t1[AUTHOR];
__device__ unsigned char g_flag[AUTHOR];
__device__ __align__(16) float g_u0[132];   // u[128] + c at [128]
__device__ __align__(16) float g_u1[132];
// k-major matrices: M[k*128 + d]  (coalesced per-warp weight loads in k_both)
__device__ float g_W3T[DIM * DIM];
__device__ float g_W4T[DIM * DIM];
__device__ float g_M6[DIM * DIM];
__device__ float g_M9[DIM * DIM];
__device__ float g_M7[DIM * DIM];
__device__ float g_M10[DIM * DIM];
__device__ float g_M12[DIM * DIM];
__device__ float g_bf[DIM];
__device__ float g_h[BATCH * DIM];

// ---------------- packed f32x2 helpers ----------------
__device__ __forceinline__ ull pk(float lo, float hi) {
    ull r; asm("mov.b64 %0, {%1,%2};" : "=l"(r) : "f"(lo), "f"(hi)); return r;
}
__device__ __forceinline__ ull dup2(float v) { return pk(v, v); }
__device__ __forceinline__ ull ffma2(ull a, ull b, ull c) {
    ull r; asm("fma.rn.f32x2 %0, %1, %2, %3;" : "=l"(r) : "l"(a), "l"(b), "l"(c)); return r;
}
__device__ __forceinline__ float2 upk(ull v) {
    float2 f; asm("mov.b64 {%0,%1}, %2;" : "=f"(f.x), "=f"(f.y) : "l"(v)); return f;
}

// ---------------- fused setup kernel ----------------
#define ZB  196
#define UB  2
#define FB  320
#define TB  128
#define BFB 128
#define OB  32
#define SETUP_BLOCKS (ZB + UB + FB + TB + BFB + OB)

__global__ void __launch_bounds__(256) k_setup(
        const float* __restrict__ W3, const float* __restrict__ hp0, const float* __restrict__ b3,
        const float* __restrict__ W4, const float* __restrict__ hp1, const float* __restrict__ b4,
        const float* __restrict__ Wc, const float* __restrict__ bc,
        const float* __restrict__ W6, const float* __restrict__ b6,
        const float* __restrict__ W9, const float* __restrict__ b9,
        const float* __restrict__ W7, const float* __restrict__ b7,
        const float* __restrict__ W10, const float* __restrict__ b10,
        const float* __restrict__ W12, const float* __restrict__ b12,
        const float* __restrict__ b2, float* __restrict__ out) {
    __shared__ float red[256];
    int bx = blockIdx.x, tid = threadIdx.x;

    if (bx < ZB) {                                   // ---- zero flags
        int i = bx * 256 + tid;
        if (i < AUTHOR) g_flag[i] = 0;
        return;
    }
    bx -= ZB;
    if (bx < UB) {                                   // ---- u = W^T hp, c = b.hp
        const float* W  = bx ? W4  : W3;
        const float* hp = bx ? hp1 : hp0;
        const float* bb = bx ? b4  : b3;
        float* u = bx ? g_u1 : g_u0;
        int k = tid;
        if (k < DIM) {
            float a = 0.f;
            #pragma unroll 8
            for (int d = 0; d < DIM; d++) a += W[d * DIM + k] * hp[d];
            u[k] = a;
            red[k] = bb[k] * hp[k];
        }
        __syncthreads();
        if (k < DIM) {
            for (int s = 64; s; s >>= 1) {
                if (k < s) red[k] += red[k + s];
                __syncwarp(0xffffffffu);
                if (s > 32) __syncthreads();
            }
            if (k == 0) u[DIM] = red[0];
        }
        return;
    }
    bx -= UB;
    if (bx < FB) {                                   // ---- fused M matrices (k-major store)
        int m = bx / 64;
        const float* R; float* M; int seg;
        switch (m) {
            case 0:  R = W6;  M = g_M6;  seg = 0; break;
            case 1:  R = W9;  M = g_M9;  seg = 0; break;
            case 2:  R = W7;  M = g_M7;  seg = 1; break;
            case 3:  R = W10; M = g_M10; seg = 1; break;
            default: R = W12; M = g_M12; seg = 2; break;
        }
        int o = (bx % 64) * 256 + tid;
        int d = o >> 7, k = o & 127;
        const float* wrow = Wc + (size_t)d * 384 + seg * 128;
        float a = 0.f;
        #pragma unroll 8
        for (int j = 0; j < DIM; j++) a += wrow[j] * R[j * DIM + k];
        M[k * DIM + d] = a;
        return;
    }
    bx -= FB;
    if (bx < TB) {                                   // ---- transpose W3, W4 to k-major
        int m = bx / 64;
        const float* W = m ? W4 : W3;
        float* T = m ? g_W4T : g_W3T;
        int o = (bx % 64) * 256 + tid;
        int d = o >> 7, k = o & 127;
        T[k * DIM + d] = W[o];
        return;
    }
    bx -= TB;
    if (bx < BFB) {                                  // ---- fused bias
        int i = bx;
        const float* w = Wc + (size_t)i * 384;
        float a = 0.f;
        {
            int j = tid;
            float v = (j < 128) ? (b6[j] + b9[j]) : (b7[j - 128] + b10[j - 128]);
            a = w[j] * v;
            if (tid < 128) a += w[256 + tid] * b12[tid];
        }
        red[tid] = a;
        __syncthreads();
        for (int s = 128; s > 32; s >>= 1) {
            if (tid < s) red[tid] += red[tid + s];
            __syncthreads();
        }
        if (tid < 32) {
            float v = red[tid] + red[tid + 32];
            #pragma unroll
            for (int o = 16; o; o >>= 1) v += __shfl_xor_sync(0xffffffffu, v, o);
            if (tid == 0) g_bf[i] = v + bc[i];
        }
        return;
    }
    bx -= BFB;
    {                                                // ---- init out with b2
        int idx = bx * 256 + tid;
        out[idx] = b2[idx & 1];
    }
}

// mark needed author rows; zero their accumulators
__global__ void k_mark(const int* __restrict__ data) {
    int tid = blockIdx.x * blockDim.x + threadIdx.x;
    int b = tid >> 7, d = tid & 127;
    int r = data[b];
    g_s0[(size_t)r * DIM + d] = 0.f;
    g_s1[(size_t)r * DIM + d] = 0.f;
    if (d == 0) { g_t0[r] = 0.f; g_t1[r] = 0.f; g_flag[r] = 1; }
}

// ---------------- edge kernel: filter + weighted scatter (both graphs) ----------------
__global__ void k_edges(const int* __restrict__ ei0, const float* __restrict__ iv0,
                        const float* __restrict__ sem0,
                        const int* __restrict__ ei1, const float* __restrict__ iv1,
                        const float* __restrict__ sem1) {
    int which = blockIdx.y;
    const int*   rows = which ? ei1 : ei0;
    const int*   cols = (which ? ei1 : ei0) + N_EDGES;
    const float* interval = which ? iv1 : iv0;
    const float* sem = which ? sem1 : sem0;
    const float* u = which ? g_u1 : g_u0;
    float* s = which ? g_s1 : g_s0;
    float* t = which ? g_t1 : g_t0;

    cg::thread_block_tile<32> warp = cg::tiled_partition<32>(cg::this_thread_block());

    int lane = threadIdx.x & 31;
    int base = (blockIdx.x * (blockDim.x >> 5) + (threadIdx.x >> 5)) * 32;
    if (base >= N_EDGES) return;

    int e = base + lane;
    int r = -1; bool ok = false;
    if (e < N_EDGES) {
        int row = rows[e];
        r = row - META;
        ok = ((unsigned)r < (unsigned)AUTHOR) && g_flag[r];
    }
    unsigned m = __ballot_sync(0xffffffffu, ok);
    if (!m) return;

    float4 uv = ((const float4*)u)[lane];
    float c = u[DIM];
    while (m) {
        int src = __ffs(m) - 1; m &= (m - 1);
        int rr = __shfl_sync(0xffffffffu, r, src);
        int ee = base + src;
        int col = cols[ee];
        float iv = interval[ee];
        float4 x = ((const float4*)(sem + (size_t)col * DIM))[lane];
        float p = x.x * uv.x + x.y * uv.y + x.z * uv.z + x.w * uv.w;
        p = cg::reduce(warp, p, cg::plus<float>());    // REDUX.F32 on sm_100a+
        float w = __expf(iv * (p + c));
        float* sp = s + (size_t)rr * DIM + lane * 4;
        asm volatile("red.global.add.v4.f32 [%0], {%1, %2, %3, %4};"
                     :: "l"(sp), "f"(w * x.x), "f"(w * x.y), "f"(w * x.z), "f"(w * x.w)
                     : "memory");
        if (lane == 0) atomicAdd(&t[rr], w);
    }
}

// ---------------- fused dense stage (both sides + structure branch) ----------------
// 512 threads/block, 32 samples/block, 256 blocks.
// slot = tid>>7 (4 slots x 8 samples), 4 packed accumulators/thread.
#define BS     32
#define SPS    8            // samples per slot
#define PITCH  12           // floats per k-row (8 data + 4 pad; 48B keeps 16B align)
#define SLOTSZ (DIM * PITCH)

__device__ __forceinline__ void mat_pass(ull acc[4], const float* __restrict__ Mt,
                                         int d, const float* __restrict__ mybuf) {
    #pragma unroll 8
    for (int k = 0; k < DIM; k++) {
        ull wd = dup2(Mt[(size_t)k * DIM + d]);
        const ulonglong2* xp = (const ulonglong2*)(mybuf + k * PITCH);
        ulonglong2 va = xp[0], vb = xp[1];
        acc[0] = ffma2(wd, va.x, acc[0]);
        acc[1] = ffma2(wd, va.y, acc[1]);
        acc[2] = ffma2(wd, vb.x, acc[2]);
        acc[3] = ffma2(wd, vb.y, acc[3]);
    }
}

__global__ void __launch_bounds__(512) k_both(
        const float* __restrict__ b3, const float* __restrict__ c0,
        const float* __restrict__ b4, const float* __restrict__ c1,
        const float* __restrict__ st, const int* __restrict__ data) {
    __shared__ __align__(16) float buf[4 * SLOTSZ];   // 24576 B
    __shared__ float ts0[BS], ts1[BS];
    __shared__ int   rs[BS];

    int tid = threadIdx.x;
    int slot = tid >> 7, d = tid & 127;
    int bb = blockIdx.x * BS;

    if (tid < BS) {
        int r = data[bb + tid];
        rs[tid] = r;
        ts0[tid] = g_t0[r];
        ts1[tid] = g_t1[r];
    }
    __syncthreads();

    float* mybuf = buf + slot * SLOTSZ;
    int sb = slot * SPS;

    ull h2[4];
    #pragma unroll
    for (int j = 0; j < 4; j++) h2[j] = pk(0.f, 0.f);
    ull acc[4];

    // ===== side 0 =====
    for (int i = tid; i < BS * DIM; i += 512) {
        int spl = i >> 7, k = i & 127;
        buf[(spl >> 3) * SLOTSZ + k * PITCH + (spl & 7)] = g_s0[(size_t)rs[spl] * DIM + k];
    }
    __syncthreads();
    {
        float bwd = b3[d];
        #pragma unroll
        for (int j = 0; j < 4; j++)
            acc[j] = pk(ts0[sb + 2 * j] * bwd, ts0[sb + 2 * j + 1] * bwd);
        mat_pass(acc, g_W3T, d, mybuf);
    }
    __syncthreads();
    #pragma unroll
    for (int j = 0; j < 4; j++) {
        float2 gv = upk(acc[j]);
        *(ull*)(mybuf + d * PITCH + 2 * j) = pk(fmaxf(gv.x, 0.f), fmaxf(gv.y, 0.f));
    }
    __syncthreads();
    mat_pass(h2, g_M6, d, mybuf);
    __syncthreads();
    for (int i = tid; i < BS * DIM; i += 512) {
        int spl = i >> 7, k = i & 127;
        buf[(spl >> 3) * SLOTSZ + k * PITCH + (spl & 7)] = c0[(size_t)(bb + spl) * DIM + k];
    }
    __syncthreads();
    mat_pass(h2, g_M9, d, mybuf);
    __syncthreads();

    // ===== side 1 =====
    for (int i = tid; i < BS * DIM; i += 512) {
        int spl = i >> 7, k = i & 127;
        buf[(spl >> 3) * SLOTSZ + k * PITCH + (spl & 7)] = g_s1[(size_t)rs[spl] * DIM + k];
    }
    __syncthreads();
    {
        float bwd = b4[d];
        #pragma unroll
        for (int j = 0; j < 4; j++)
            acc[j] = pk(ts1[sb + 2 * j] * bwd, ts1[sb + 2 * j + 1] * bwd);
        mat_pass(acc, g_W4T, d, mybuf);
    }
    __syncthreads();
    #pragma unroll
    for (int j = 0; j < 4; j++) {
        float2 gv = upk(acc[j]);
        *(ull*)(mybuf + d * PITCH + 2 * j) = pk(fmaxf(gv.x, 0.f), fmaxf(gv.y, 0.f));
    }
    __syncthreads();
    mat_pass(h2, g_M7, d, mybuf);
    __syncthreads();
    for (int i = tid; i < BS * DIM; i += 512) {
        int spl = i >> 7, k = i & 127;
        buf[(spl >> 3) * SLOTSZ + k * PITCH + (spl & 7)] = c1[(size_t)(bb + spl) * DIM + k];
    }
    __syncthreads();
    mat_pass(h2, g_M10, d, mybuf);
    __syncthreads();

    // ===== structure branch + relu =====
    for (int i = tid; i < BS * DIM; i += 512) {
        int spl = i >> 7, k = i & 127;
        buf[(spl >> 3) * SLOTSZ + k * PITCH + (spl & 7)] = st[(size_t)(bb + spl) * DIM + k];
    }
    __syncthreads();
    mat_pass(h2, g_M12, d, mybuf);
    float bfd = g_bf[d];
    #pragma unroll
    for (int j = 0; j < 4; j++) {
        float2 hv = upk(h2[j]);
        g_h[(size_t)(bb + sb + 2 * j) * DIM + d]     = fmaxf(hv.x + bfd, 0.f);
        g_h[(size_t)(bb + sb + 2 * j + 1) * DIM + d] = fmaxf(hv.y + bfd, 0.f);
    }
}

// ---------------- pair stage, split over z-quarters; atomic combine ----------------
#define DPITCH 66
#define HQ     (HID / 4)
__global__ void __launch_bounds__(256) k_pairs(
        const float* __restrict__ W1, const float* __restrict__ b1,
        const float* __restrict__ W2,
        float* __restrict__ out) {
    __shared__ __align__(16) float dT[DIM * DPITCH];
    __shared__ float w1c[8 * DIM];
    __shared__ ull red0[8][32];
    __shared__ ull red1[8][32];

    int tid = threadIdx.x;
    int p = tid & 31, zs = tid >> 5;
    int pbase = blockIdx.x * 64;
    int zbase = blockIdx.y * HQ;

    for (int e = tid; e < 8192; e += 256) {
        int pp = e >> 7, k = e & 127;
        float a  = g_h[(size_t)(pbase + pp) * DIM + k];
        float bq = g_h[(size_t)(pbase + pp + PAIRS) * DIM + k];
        dT[k * DPITCH + pp] = fabsf(a - bq);
    }
    __syncthreads();

    ull o0 = pk(0.f, 0.f), o1 = pk(0.f, 0.f);
    const ull* drow = (const ull*)dT;
    for (int zc = 0; zc < HQ / 8; zc++) {
        for (int e = tid; e < 1024; e += 256) {
            int zz = e >> 7, k = e & 127;
            w1c[zz * DIM + k] = W1[(size_t)(zbase + zc * 8 + zz) * DIM + k];
        }
        __syncthreads();
        ull acc = pk(0.f, 0.f);
        #pragma unroll 8
        for (int k = 0; k < DIM; k++)
            acc = ffma2(dup2(w1c[zs * DIM + k]), drow[k * (DPITCH / 2) + p], acc);
        int z = zbase + zc * 8 + zs;
        float bz = b1[z];
        float2 av = upk(acc);
        ull zv = pk(fmaxf(av.x + bz, 0.f), fmaxf(av.y + bz, 0.f));
        o0 = ffma2(dup2(W2[z]),       zv, o0);
        o1 = ffma2(dup2(W2[HID + z]), zv, o1);
        __syncthreads();
    }
    red0[zs][p] = o0; red1[zs][p] = o1;
    __syncthreads();
    if (zs == 0) {
        float a0 = 0.f, a1 = 0.f, c0 = 0.f, c1 = 0.f;
        #pragma unroll
        for (int j = 0; j < 8; j++) {
            float2 v0 = upk(red0[j][p]); a0 += v0.x; c0 += v0.y;
            float2 v1 = upk(red1[j][p]); a1 += v1.x; c1 += v1.y;
        }
        int q0 = pbase + 2 * p, q1 = q0 + 1;
        atomicAdd(&out[(size_t)q0 * 2 + 0], a0);
        atomicAdd(&out[(size_t)q0 * 2 + 1], a1);
        atomicAdd(&out[(size_t)q1 * 2 + 0], c0);
        atomicAdd(&out[(size_t)q1 * 2 + 1], c1);
    }
}

// ---------------- launch ----------------
extern "C" void kernel_launch(void* const* d_in, const int* in_sizes, int n_in,
                              void* d_out, int out_size) {
    const float* sem0 = (const float*)d_in[0];
    const float* iv0  = (const float*)d_in[1];
    const int*   ei0  = (const int*)  d_in[2];
    const float* sem1 = (const float*)d_in[3];
    const float* iv1  = (const float*)d_in[4];
    const int*   ei1  = (const int*)  d_in[5];
    const float* c0   = (const float*)d_in[6];
    const float* c1   = (const float*)d_in[7];
    const int*   data = (const int*)  d_in[8];
    const float* st   = (const float*)d_in[9];
    const float* W1  = (const float*)d_in[10]; const float* b1  = (const float*)d_in[11];
    const float* W2  = (const float*)d_in[12]; const float* b2  = (const float*)d_in[13];
    const float* W3  = (const float*)d_in[14]; const float* b3  = (const float*)d_in[15];
    const float* W4  = (const float*)d_in[16]; const float* b4  = (const float*)d_in[17];
    const float* W6  = (const float*)d_in[18]; const float* b6  = (const float*)d_in[19];
    const float* W7  = (const float*)d_in[20]; const float* b7  = (const float*)d_in[21];
    const float* W9  = (const float*)d_in[22]; const float* b9  = (const float*)d_in[23];
    const float* W10 = (const float*)d_in[24]; const float* b10 = (const float*)d_in[25];
    const float* W12 = (const float*)d_in[26]; const float* b12 = (const float*)d_in[27];
    const float* Wc  = (const float*)d_in[28]; const float* bc  = (const float*)d_in[29];
    const float* hp0 = (const float*)d_in[30]; const float* hp1 = (const float*)d_in[31];
    float* out = (float*)d_out;

    k_setup<<<SETUP_BLOCKS, 256>>>(W3, hp0, b3, W4, hp1, b4, Wc, bc,
                                   W6, b6, W9, b9, W7, b7, W10, b10, W12, b12,
                                   b2, out);
    k_mark<<<(BATCH * DIM) / 256, 256>>>(data);

    int eblocks = (N_EDGES / 32 + 7) / 8;
    k_edges<<<dim3(eblocks, 2), 256>>>(ei0, iv0, sem0, ei1, iv1, sem1);

    k_both<<<BATCH / BS, 512>>>(b3, c0, b4, c1, st, data);

    k_pairs<<<dim3(PAIRS / 64, 4), 256>>>(W1, b1, W2, out);
    (void)in_sizes; (void)n_in; (void)out_size;
}